// round 2
// baseline (speedup 1.0000x reference)
#include <cuda_runtime.h>
#include <math.h>

#define BB 32
#define TT 512
#define HH 1024
#define LL 256
#define VV 13

// ---- scratch (static device globals: no allocation allowed) ----
__device__ float g_h0[BB * HH];                 // 128 KB
__device__ float g_c[BB * HH];                  // 128 KB
__device__ float g_hs[(size_t)BB * TT * HH];    // 64 MB, layout [b][t][h]
__device__ float g_part[512];                   // per-CTA loss partials (16 CTAs per b)

// ------------------------------------------------------------------
// zero c state
// ------------------------------------------------------------------
__global__ void k_zero() {
    int i = blockIdx.x * blockDim.x + threadIdx.x;
    if (i < BB * HH) g_c[i] = 0.f;
}

// ------------------------------------------------------------------
// h0 = relu(latent @ Wz^T + bz)
// ------------------------------------------------------------------
__global__ void k_h0(const float* __restrict__ latent,
                     const float* __restrict__ Wz,
                     const float* __restrict__ bz) {
    __shared__ float lat[LL];
    int b = blockIdx.x;
    for (int k = threadIdx.x; k < LL; k += blockDim.x) lat[k] = latent[b * LL + k];
    __syncthreads();
    for (int j = threadIdx.x; j < HH; j += blockDim.x) {
        const float4* w = (const float4*)(Wz + (size_t)j * LL);
        float s = bz[j];
#pragma unroll 8
        for (int k4 = 0; k4 < LL / 4; ++k4) {
            float4 wv = w[k4];
            s += wv.x * lat[k4 * 4 + 0] + wv.y * lat[k4 * 4 + 1]
               + wv.z * lat[k4 * 4 + 2] + wv.w * lat[k4 * 4 + 3];
        }
        g_h0[b * HH + j] = fmaxf(s, 0.f);
    }
}

// ------------------------------------------------------------------
// One LSTM timestep. 128 CTAs x 128 threads.
// CTA m owns units [m*8, m*8+8): 32 gate rows (4 gates per unit),
// so gate GEMM + pointwise are CTA-local (no inter-CTA dependency).
// ------------------------------------------------------------------
#define KC 64
#define AP 68   // As row pitch (floats): 68*4B = 17*16B, float4-aligned
#define BP 34   // Bs row pitch (k-major), even for float2 reads

__global__ __launch_bounds__(128) void k_step(
    int t,
    const float* __restrict__ W_hh,   // [4H, H]
    const float* __restrict__ W_ih,   // [4H, V]
    const float* __restrict__ b_ih,
    const float* __restrict__ b_hh,
    const int*   __restrict__ labels) // [B, T]
{
    __shared__ float As[32 * AP];     // W_hh tile: rows (g*8+ul) x KC
    __shared__ float Bs[KC * BP];     // h_prev tile transposed: [k][b]

    const int tid = threadIdx.x;
    const int tx = tid & 15;          // batch pair 0..15
    const int ty = tid >> 4;          // local unit 0..7
    const int u0 = blockIdx.x * 8;

    float acc[4][2] = {};

    for (int kc = 0; kc < HH; kc += KC) {
        // stage A: 32 rows x 64 = 512 float4, 4 per thread
#pragma unroll
        for (int q = 0; q < 4; ++q) {
            int i = tid + q * 128;
            int row = i >> 4;                  // 0..31
            int kq = (i & 15) << 2;            // 0..60
            int g = row >> 3, ul = row & 7;
            float4 v = *(const float4*)(W_hh + (size_t)(g * HH + u0 + ul) * HH + kc + kq);
            *(float4*)(As + row * AP + kq) = v;
        }
        // stage B (transposed): 32 b x 64 k = 2048 floats, 16 per thread
#pragma unroll
        for (int q = 0; q < 16; ++q) {
            int i = q * 128 + tid;
            int k = i & (KC - 1);
            int b = i >> 6;
            float v;
            if (t == 0) v = g_h0[b * HH + kc + k];
            else        v = g_hs[((size_t)b * TT + (t - 1)) * HH + kc + k];
            Bs[k * BP + b] = v;
        }
        __syncthreads();

#pragma unroll 8
        for (int k = 0; k < KC; ++k) {
            float2 bb = *(const float2*)(Bs + k * BP + (tx << 1));
            float a0 = As[(0 * 8 + ty) * AP + k];
            float a1 = As[(1 * 8 + ty) * AP + k];
            float a2 = As[(2 * 8 + ty) * AP + k];
            float a3 = As[(3 * 8 + ty) * AP + k];
            acc[0][0] += a0 * bb.x; acc[0][1] += a0 * bb.y;
            acc[1][0] += a1 * bb.x; acc[1][1] += a1 * bb.y;
            acc[2][0] += a2 * bb.x; acc[2][1] += a2 * bb.y;
            acc[3][0] += a3 * bb.x; acc[3][1] += a3 * bb.y;
        }
        __syncthreads();
    }

    // pointwise LSTM cell update (torch gate order: i, f, g, o)
    const int unit = u0 + ty;
#pragma unroll
    for (int n = 0; n < 2; ++n) {
        const int b = (tx << 1) + n;
        float gate[4];
        int lbl = (t > 0) ? labels[b * TT + t - 1] : 0;
#pragma unroll
        for (int g = 0; g < 4; ++g) {
            int row = g * HH + unit;
            float x = acc[g][n] + b_ih[row] + b_hh[row];
            if (t > 0) x += W_ih[row * VV + lbl];   // one-hot input = column gather
            gate[g] = x;
        }
        float ig = 1.f / (1.f + expf(-gate[0]));
        float fg = 1.f / (1.f + expf(-gate[1]));
        float gg = tanhf(gate[2]);
        float og = 1.f / (1.f + expf(-gate[3]));
        size_t cidx = (size_t)b * HH + unit;
        float c = fg * g_c[cidx] + ig * gg;
        g_c[cidx] = c;
        g_hs[((size_t)b * TT + t) * HH + unit] = og * tanhf(c);
    }
}

// ------------------------------------------------------------------
// Output head, fused: a = relu([h,lat] @ Wnl^T + bnl) ;
// logits = a @ Wout^T + bout ; nll at label ; masked sum.
// One CTA = 32 consecutive (b,t) rows (same b). 512 CTAs x 128 threads.
// ------------------------------------------------------------------
#define OKC 32
#define FP 33   // Fs pitch
#define WT 68   // Wst pitch: 68*4B = 17*16B, float4-aligned
#define ASP 66  // aS pitch
#define WOP 66  // Wos pitch

__global__ __launch_bounds__(128) void k_out(
    const float* __restrict__ latent,
    const int*   __restrict__ labels,
    const int*   __restrict__ lengths,
    const float* __restrict__ Wnl,   // [H, H+L]
    const float* __restrict__ bnl,   // [H]
    const float* __restrict__ Wout,  // [V, H]
    const float* __restrict__ bout)  // [V]
{
    __shared__ float Fs[32 * FP];        // feature tile [row][k]
    __shared__ float Wst[OKC * WT];      // Wnl tile transposed [k][jl]
    __shared__ float aS[32 * ASP];       // relu activations [row][jl]
    __shared__ float Wos[VV * WOP];      // Wout chunk [v][jl]
    __shared__ float Ls[32 * 16];        // logits accumulators
    __shared__ float lat_s[LL];
    __shared__ float red[4];

    const int tid = threadIdx.x;
    const int r0 = blockIdx.x * 32;      // global row = b*T + t
    const int b = r0 / TT;
    const int txj = tid & 15;            // j group (4 each)
    const int tyr = tid >> 4;            // row group (4 each)

    for (int idx = tid; idx < 32 * 16; idx += 128) Ls[idx] = 0.f;
    for (int k = tid; k < LL; k += 128) lat_s[k] = latent[b * LL + k];

    for (int jc = 0; jc < HH; jc += 64) {
        float acc[4][4] = {};
        for (int kc = 0; kc < HH + LL; kc += OKC) {
            __syncthreads();
            // stage features: 32 rows x 32 k
#pragma unroll
            for (int q = 0; q < 8; ++q) {
                int i = q * 128 + tid;
                int k = i & 31;
                int row = i >> 5;
                int kk = kc + k;
                float v = (kk < HH) ? g_hs[(size_t)(r0 + row) * HH + kk]
                                    : lat_s[kk - HH];
                Fs[row * FP + k] = v;
            }
            // stage Wnl transposed: 64 j x 32 k
#pragma unroll
            for (int q = 0; q < 4; ++q) {
                int i = q * 128 + tid;           // 0..511 float4
                int jl = i >> 3;                 // 0..63
                int kq = (i & 7) << 2;           // 0..28
                float4 v = *(const float4*)(Wnl + (size_t)(jc + jl) * (HH + LL) + kc + kq);
                Wst[(kq + 0) * WT + jl] = v.x;
                Wst[(kq + 1) * WT + jl] = v.y;
                Wst[(kq + 2) * WT + jl] = v.z;
                Wst[(kq + 3) * WT + jl] = v.w;
            }
            __syncthreads();
#pragma unroll 4
            for (int k = 0; k < OKC; ++k) {
                float4 wv = *(const float4*)(Wst + k * WT + (txj << 2));
                float f0 = Fs[(tyr * 4 + 0) * FP + k];
                float f1 = Fs[(tyr * 4 + 1) * FP + k];
                float f2 = Fs[(tyr * 4 + 2) * FP + k];
                float f3 = Fs[(tyr * 4 + 3) * FP + k];
                acc[0][0] += f0 * wv.x; acc[0][1] += f0 * wv.y; acc[0][2] += f0 * wv.z; acc[0][3] += f0 * wv.w;
                acc[1][0] += f1 * wv.x; acc[1][1] += f1 * wv.y; acc[1][2] += f1 * wv.z; acc[1][3] += f1 * wv.w;
                acc[2][0] += f2 * wv.x; acc[2][1] += f2 * wv.y; acc[2][2] += f2 * wv.z; acc[2][3] += f2 * wv.w;
                acc[3][0] += f3 * wv.x; acc[3][1] += f3 * wv.y; acc[3][2] += f3 * wv.z; acc[3][3] += f3 * wv.w;
            }
        }
        __syncthreads();
        // relu + bias -> aS ; stage Wout chunk
#pragma unroll
        for (int ri = 0; ri < 4; ++ri)
#pragma unroll
            for (int ji = 0; ji < 4; ++ji) {
                int j = (txj << 2) + ji;
                aS[(tyr * 4 + ri) * ASP + j] = fmaxf(acc[ri][ji] + bnl[jc + j], 0.f);
            }
        for (int idx = tid; idx < VV * 64; idx += 128) {
            int v = idx >> 6, jl = idx & 63;
            Wos[v * WOP + jl] = Wout[(size_t)v * HH + jc + jl];
        }
        __syncthreads();
        // logits accumulation (tiny GEMM to V=13)
        for (int idx = tid; idx < 32 * VV; idx += 128) {
            int row = idx / VV, v = idx - row * VV;
            float s = 0.f;
#pragma unroll 8
            for (int jl = 0; jl < 64; ++jl)
                s += aS[row * ASP + jl] * Wos[v * WOP + jl];
            Ls[row * 16 + v] += s;
        }
        __syncthreads();
    }

    // log-softmax + masked NLL, reduce to one partial per CTA (deterministic)
    float val = 0.f;
    if (tid < 32) {
        int row = tid;
        int t = (r0 + row) % TT;
        float m = -1e30f;
#pragma unroll
        for (int v = 0; v < VV; ++v) m = fmaxf(m, Ls[row * 16 + v] + bout[v]);
        float s = 0.f;
#pragma unroll
        for (int v = 0; v < VV; ++v) s += expf(Ls[row * 16 + v] + bout[v] - m);
        float lse = m + logf(s);
        int lbl = labels[b * TT + t];
        float nll = lse - (Ls[row * 16 + lbl] + bout[lbl]);
        if (t < lengths[b]) val = nll;
#pragma unroll
        for (int o = 16; o > 0; o >>= 1) val += __shfl_down_sync(0xffffffffu, val, o);
        if (row == 0) g_part[blockIdx.x] = val;
    }
}

// ------------------------------------------------------------------
// finalize: out[1+b] = sum of 16 partials ; out[0] = total
// ------------------------------------------------------------------
__global__ void k_final(float* __restrict__ out, int out_size) {
    int b = threadIdx.x;   // 0..31
    float s = 0.f;
#pragma unroll
    for (int i = 0; i < 16; ++i) s += g_part[b * 16 + i];
    if (1 + b < out_size) out[1 + b] = s;
    float tot = s;
#pragma unroll
    for (int o = 16; o > 0; o >>= 1) tot += __shfl_down_sync(0xffffffffu, tot, o);
    if (b == 0) out[0] = tot;
}

// ------------------------------------------------------------------
extern "C" void kernel_launch(void* const* d_in, const int* in_sizes, int n_in,
                              void* d_out, int out_size) {
    // metadata order = setup_inputs dict order
    // 0: seq_input (unused — one-hot reconstructed from labels)
    const float* latent  = (const float*)d_in[1];
    const int*   labels  = (const int*)d_in[2];
    const int*   lengths = (const int*)d_in[3];
    const float* W_ih    = (const float*)d_in[4];
    const float* W_hh    = (const float*)d_in[5];
    const float* b_ih    = (const float*)d_in[6];
    const float* b_hh    = (const float*)d_in[7];
    const float* Wz      = (const float*)d_in[8];
    const float* bz      = (const float*)d_in[9];
    const float* Wnl     = (const float*)d_in[10];
    const float* bnl     = (const float*)d_in[11];
    const float* Wout    = (const float*)d_in[12];
    const float* bout    = (const float*)d_in[13];
    float* out = (float*)d_out;

    k_zero<<<(BB * HH + 255) / 256, 256>>>();
    k_h0<<<BB, 256>>>(latent, Wz, bz);
    for (int t = 0; t < TT; ++t)
        k_step<<<128, 128>>>(t, W_hh, W_ih, b_ih, b_hh, labels);
    k_out<<<(BB * TT) / 32, 128>>>(latent, labels, lengths, Wnl, bnl, Wout, bout);
    k_final<<<1, 32>>>(out, out_size);
}